// round 2
// baseline (speedup 1.0000x reference)
#include <cuda_runtime.h>

#define N_NODES 90000
#define N_EDGES 540000
#define IN_F    30
#define N_GRAPH 10000

// ---------------- scratch (static __device__, no allocation) ----------------
__device__ float g_agg0[N_NODES * 32];        // x + sum(x[src]) padded to 32
__device__ float g_z1s[N_NODES * 128];
__device__ float g_z1t[N_NODES * 128];
__device__ float g_agg1s[N_NODES * 128];
__device__ float g_agg1t[N_NODES * 128];
__device__ float g_z2s[N_NODES * 64];
__device__ float g_z2t[N_NODES * 64];
__device__ int   g_deg[N_NODES];
__device__ int   g_cursor[N_NODES];
__device__ int   g_rowptr[N_NODES + 1];
__device__ int   g_csrsrc[N_EDGES];

// ---------------- CSR build ----------------
__global__ void zero_kernel() {
    int i = blockIdx.x * blockDim.x + threadIdx.x;
    if (i < N_NODES) { g_deg[i] = 0; g_cursor[i] = 0; }
}

__global__ void hist_kernel(const int* __restrict__ ei) {
    int e = blockIdx.x * blockDim.x + threadIdx.x;
    if (e < N_EDGES) {
        int dst = ei[N_EDGES + e];
        atomicAdd(&g_deg[dst], 1);
    }
}

// one-block exclusive scan over 90000 degrees
__global__ void scan_kernel() {
    const int CHUNK = (N_NODES + 1023) / 1024;   // 88
    __shared__ int part[1024];
    int t = threadIdx.x;
    int start = t * CHUNK;
    int s = 0;
    for (int i = 0; i < CHUNK; i++) {
        int idx = start + i;
        if (idx < N_NODES) s += g_deg[idx];
    }
    part[t] = s;
    __syncthreads();
    // Hillis-Steele inclusive scan
    for (int off = 1; off < 1024; off <<= 1) {
        int v = (t >= off) ? part[t - off] : 0;
        __syncthreads();
        part[t] += v;
        __syncthreads();
    }
    int run = (t > 0) ? part[t - 1] : 0;   // exclusive prefix
    for (int i = 0; i < CHUNK; i++) {
        int idx = start + i;
        if (idx < N_NODES) { g_rowptr[idx] = run; run += g_deg[idx]; }
    }
    if (t == 1023) g_rowptr[N_NODES] = part[1023];
}

__global__ void fill_kernel(const int* __restrict__ ei) {
    int e = blockIdx.x * blockDim.x + threadIdx.x;
    if (e < N_EDGES) {
        int src = ei[e];
        int dst = ei[N_EDGES + e];
        int pos = g_rowptr[dst] + atomicAdd(&g_cursor[dst], 1);
        g_csrsrc[pos] = src;
    }
}

// ---------------- layer-1 aggregation (shared by both branches) ----------------
// warp per node; lanes 0..29 carry features, 30/31 write zero padding
__global__ void agg0_kernel(const float* __restrict__ x) {
    int w = (blockIdx.x * blockDim.x + threadIdx.x) >> 5;
    int lane = threadIdx.x & 31;
    if (w >= N_NODES) return;
    float acc = (lane < IN_F) ? x[w * IN_F + lane] : 0.f;
    int s0 = g_rowptr[w], s1 = g_rowptr[w + 1];
    for (int e = s0; e < s1; e++) {
        int s = g_csrsrc[e];
        if (lane < IN_F) acc += x[s * IN_F + lane];
    }
    g_agg0[w * 32 + lane] = acc;
}

// ---------------- fused MLP1: [N,30] -> relu(@W1+b1) -> @W2+b2 -> [N,128] ----------------
__global__ __launch_bounds__(256) void mlp1_kernel(
    const float* __restrict__ w1, const float* __restrict__ b1,
    const float* __restrict__ w2, const float* __restrict__ b2, int br)
{
    __shared__ float a_s[32][32];
    __shared__ float h_s[32][128];
    float* z1 = br ? g_z1t : g_z1s;

    int row0 = blockIdx.x * 32;
    int tid = threadIdx.x;

    // stage A tile (32 rows x 32 padded cols)
    {
        int r = tid >> 3, c = (tid & 7) << 2;
        int gr = row0 + r;
        float4 v = (gr < N_NODES) ? *(const float4*)&g_agg0[gr * 32 + c]
                                  : make_float4(0.f, 0.f, 0.f, 0.f);
        *(float4*)&a_s[r][c] = v;
    }
    __syncthreads();

    // stage 1: H = relu(A @ W1 + b1), K=30, Nout=128
    {
        int j0 = (tid & 31) << 2, r0 = (tid >> 5) << 2;
        float acc[4][4] = {};
        #pragma unroll
        for (int k = 0; k < IN_F; k++) {
            float4 wv = *(const float4*)&w1[k * 128 + j0];
            #pragma unroll
            for (int r = 0; r < 4; r++) {
                float a = a_s[r0 + r][k];
                acc[r][0] += a * wv.x; acc[r][1] += a * wv.y;
                acc[r][2] += a * wv.z; acc[r][3] += a * wv.w;
            }
        }
        float4 bv = *(const float4*)&b1[j0];
        #pragma unroll
        for (int r = 0; r < 4; r++) {
            float4 h;
            h.x = fmaxf(acc[r][0] + bv.x, 0.f);
            h.y = fmaxf(acc[r][1] + bv.y, 0.f);
            h.z = fmaxf(acc[r][2] + bv.z, 0.f);
            h.w = fmaxf(acc[r][3] + bv.w, 0.f);
            *(float4*)&h_s[r0 + r][j0] = h;
        }
    }
    __syncthreads();

    // stage 2: Z = H @ W2 + b2, K=128, Nout=128
    {
        int j0 = (tid & 31) << 2, r0 = (tid >> 5) << 2;
        float acc[4][4] = {};
        #pragma unroll 4
        for (int k = 0; k < 128; k++) {
            float4 wv = *(const float4*)&w2[k * 128 + j0];
            #pragma unroll
            for (int r = 0; r < 4; r++) {
                float h = h_s[r0 + r][k];
                acc[r][0] += h * wv.x; acc[r][1] += h * wv.y;
                acc[r][2] += h * wv.z; acc[r][3] += h * wv.w;
            }
        }
        float4 bv = *(const float4*)&b2[j0];
        #pragma unroll
        for (int r = 0; r < 4; r++) {
            int gr = row0 + r0 + r;
            if (gr < N_NODES) {
                float4 o;
                o.x = acc[r][0] + bv.x; o.y = acc[r][1] + bv.y;
                o.z = acc[r][2] + bv.z; o.w = acc[r][3] + bv.w;
                *(float4*)&z1[gr * 128 + j0] = o;
            }
        }
    }
}

// ---------------- layer-2 aggregation: agg1 = z1 + segment_sum(z1[src]) ----------------
__global__ void agg1_kernel(int br) {
    const float4* z = (const float4*)(br ? g_z1t : g_z1s);
    float4* a = (float4*)(br ? g_agg1t : g_agg1s);
    int w = (blockIdx.x * blockDim.x + threadIdx.x) >> 5;
    int lane = threadIdx.x & 31;
    if (w >= N_NODES) return;
    float4 acc = z[w * 32 + lane];
    int s0 = g_rowptr[w], s1 = g_rowptr[w + 1];
    for (int e = s0; e < s1; e++) {
        int s = g_csrsrc[e];
        float4 v = z[s * 32 + lane];
        acc.x += v.x; acc.y += v.y; acc.z += v.z; acc.w += v.w;
    }
    a[w * 32 + lane] = acc;
}

// ---------------- fused MLP2: [N,128] -> relu(@W3+b3) -> @W4+b4 -> [N,64] ----------------
__global__ __launch_bounds__(256) void mlp2_kernel(
    const float* __restrict__ w3, const float* __restrict__ b3,
    const float* __restrict__ w4, const float* __restrict__ b4, int br)
{
    __shared__ float a_s[32][128];
    __shared__ float h_s[32][128];
    const float* agg = br ? g_agg1t : g_agg1s;
    float* z2 = br ? g_z2t : g_z2s;

    int row0 = blockIdx.x * 32;
    int tid = threadIdx.x;

    // stage A tile (32 x 128)
    for (int i = tid; i < 1024; i += 256) {
        int r = i >> 5, c = (i & 31) << 2;
        int gr = row0 + r;
        float4 v = (gr < N_NODES) ? *(const float4*)&agg[gr * 128 + c]
                                  : make_float4(0.f, 0.f, 0.f, 0.f);
        *(float4*)&a_s[r][c] = v;
    }
    __syncthreads();

    // stage 1: H = relu(A @ W3 + b3), K=128, Nout=128
    {
        int j0 = (tid & 31) << 2, r0 = (tid >> 5) << 2;
        float acc[4][4] = {};
        #pragma unroll 4
        for (int k = 0; k < 128; k++) {
            float4 wv = *(const float4*)&w3[k * 128 + j0];
            #pragma unroll
            for (int r = 0; r < 4; r++) {
                float a = a_s[r0 + r][k];
                acc[r][0] += a * wv.x; acc[r][1] += a * wv.y;
                acc[r][2] += a * wv.z; acc[r][3] += a * wv.w;
            }
        }
        float4 bv = *(const float4*)&b3[j0];
        #pragma unroll
        for (int r = 0; r < 4; r++) {
            float4 h;
            h.x = fmaxf(acc[r][0] + bv.x, 0.f);
            h.y = fmaxf(acc[r][1] + bv.y, 0.f);
            h.z = fmaxf(acc[r][2] + bv.z, 0.f);
            h.w = fmaxf(acc[r][3] + bv.w, 0.f);
            *(float4*)&h_s[r0 + r][j0] = h;
        }
    }
    __syncthreads();

    // stage 2: Z = H @ W4 + b4, K=128, Nout=64
    {
        int j0 = (tid & 15) << 2, r0 = (tid >> 4) << 1;
        float acc[2][4] = {};
        #pragma unroll 4
        for (int k = 0; k < 128; k++) {
            float4 wv = *(const float4*)&w4[k * 64 + j0];
            #pragma unroll
            for (int r = 0; r < 2; r++) {
                float h = h_s[r0 + r][k];
                acc[r][0] += h * wv.x; acc[r][1] += h * wv.y;
                acc[r][2] += h * wv.z; acc[r][3] += h * wv.w;
            }
        }
        float4 bv = *(const float4*)&b4[j0];
        #pragma unroll
        for (int r = 0; r < 2; r++) {
            int gr = row0 + r0 + r;
            if (gr < N_NODES) {
                float4 o;
                o.x = acc[r][0] + bv.x; o.y = acc[r][1] + bv.y;
                o.z = acc[r][2] + bv.z; o.w = acc[r][3] + bv.w;
                *(float4*)&z2[gr * 64 + j0] = o;
            }
        }
    }
}

// ---------------- per-graph 9x9 gram: out[g*9+i][j] = <zs[g,i], zt[g,j]> ----------------
__global__ void final_kernel(float* __restrict__ out) {
    __shared__ float zs[9 * 64];
    __shared__ float zt[9 * 64];
    int g = blockIdx.x;
    const float4* ps = (const float4*)(g_z2s + g * 9 * 64);
    const float4* pt = (const float4*)(g_z2t + g * 9 * 64);
    int tid = threadIdx.x;
    for (int i = tid; i < 144; i += 128) {
        ((float4*)zs)[i] = ps[i];
        ((float4*)zt)[i] = pt[i];
    }
    __syncthreads();
    if (tid < 81) {
        int i = tid / 9, j = tid % 9;
        float acc = 0.f;
        #pragma unroll
        for (int k = 0; k < 64; k++) acc += zs[i * 64 + k] * zt[j * 64 + k];
        out[(g * 9 + i) * 9 + j] = acc;
    }
}

// ---------------- launch ----------------
extern "C" void kernel_launch(void* const* d_in, const int* in_sizes, int n_in,
                              void* d_out, int out_size) {
    const float* x   = (const float*)d_in[0];
    const int*   ei  = (const int*)d_in[1];
    const float* w1s = (const float*)d_in[2];
    const float* b1s = (const float*)d_in[3];
    const float* w2s = (const float*)d_in[4];
    const float* b2s = (const float*)d_in[5];
    const float* w3s = (const float*)d_in[6];
    const float* b3s = (const float*)d_in[7];
    const float* w4s = (const float*)d_in[8];
    const float* b4s = (const float*)d_in[9];
    const float* w1t = (const float*)d_in[10];
    const float* b1t = (const float*)d_in[11];
    const float* w2t = (const float*)d_in[12];
    const float* b2t = (const float*)d_in[13];
    const float* w3t = (const float*)d_in[14];
    const float* b3t = (const float*)d_in[15];
    const float* w4t = (const float*)d_in[16];
    const float* b4t = (const float*)d_in[17];
    float* out = (float*)d_out;

    const int MLP_BLOCKS = (N_NODES + 31) / 32;         // 2813
    const int WARP_BLOCKS = (N_NODES * 32 + 255) / 256; // warp-per-node

    zero_kernel<<<(N_NODES + 255) / 256, 256>>>();
    hist_kernel<<<(N_EDGES + 255) / 256, 256>>>(ei);
    scan_kernel<<<1, 1024>>>();
    fill_kernel<<<(N_EDGES + 255) / 256, 256>>>(ei);

    agg0_kernel<<<WARP_BLOCKS, 256>>>(x);

    mlp1_kernel<<<MLP_BLOCKS, 256>>>(w1s, b1s, w2s, b2s, 0);
    mlp1_kernel<<<MLP_BLOCKS, 256>>>(w1t, b1t, w2t, b2t, 1);

    agg1_kernel<<<WARP_BLOCKS, 256>>>(0);
    agg1_kernel<<<WARP_BLOCKS, 256>>>(1);

    mlp2_kernel<<<MLP_BLOCKS, 256>>>(w3s, b3s, w4s, b4s, 0);
    mlp2_kernel<<<MLP_BLOCKS, 256>>>(w3t, b3t, w4t, b4t, 1);

    final_kernel<<<N_GRAPH, 128>>>(out);
}